// round 6
// baseline (speedup 1.0000x reference)
#include <cuda_runtime.h>
#include <cstdint>

#define BN 512     // batch (i and j)
#define HH 512     // hidden
#define DX 128     // dim_x = dim_y

// Scratch (device globals). K is split into two halves; main adds them.
__device__ __align__(16) float hxT_g[2 * HH * BN];   // [kc][h][i]
__device__ __align__(16) float nhyT_g[2 * HH * BN];  // [kc][h][j] (negated)
__device__ __align__(16) float part_g[8 * BN * BN];  // per-h-chunk partials

// ---------------------------------------------------------------------------
// prep: one K-half (64) of the stacked GEMM [x;y] @ W1, transposed outputs.
//   x rows:  hxT_g[kc][h][r]  =  x @ W1[kc*64 : kc*64+64]   (+b1 in kc==0)
//   y rows:  nhyT_g[kc][h][r] = -(y @ W1[128+kc*64 : ...])
// grid (16 r-tiles, 8 h-tiles, 2 kc) = 256 blocks, 256 threads.
// tile 64r x 64h x 64k, thread 4r x 4h. Scalar FFMA, k batched by 4 (MLP=8).
// ---------------------------------------------------------------------------
__global__ void __launch_bounds__(256, 2) prep_kernel(
    const float* __restrict__ x, const float* __restrict__ y,
    const float* __restrict__ W1, const float* __restrict__ b1)
{
    __shared__ float As[64][64];   // [k][r]
    __shared__ float Ws[64][64];   // [k][h]

    const bool isY = (blockIdx.x >= 8);
    const int r0   = (isY ? (blockIdx.x - 8) : blockIdx.x) * 64;
    const int h0   = blockIdx.y * 64;
    const int kc   = blockIdx.z;
    const float* __restrict__ in = isY ? y : x;
    const int wrow0 = (isY ? DX : 0) + kc * 64;

    const int tid = threadIdx.x;
    const int tr  = tid & 15;    // r frag = tr*4
    const int th  = tid >> 4;    // 0..15 : h frag = th*4

    float acc[4][4] = {};        // [h][r]

    // stage input tile transposed: As[k][r]
    const int sr = tid & 63;         // row
    const int sg = tid >> 6;         // k-group (0..3)
    #pragma unroll
    for (int m = 0; m < 4; m++) {
        int k0 = sg * 16 + m * 4;
        float4 v = *(const float4*)(in + (r0 + sr) * DX + kc * 64 + k0);
        As[k0 + 0][sr] = v.x;
        As[k0 + 1][sr] = v.y;
        As[k0 + 2][sr] = v.z;
        As[k0 + 3][sr] = v.w;
    }
    // stage W1 tile [64k x 64h]
    #pragma unroll
    for (int m = 0; m < 4; m++) {
        int f = tid + 256 * m;          // float4 index 0..1023
        int k = f >> 4, q = f & 15;
        *(float4*)&Ws[k][q * 4] =
            *(const float4*)(W1 + (wrow0 + k) * HH + h0 + q * 4);
    }
    __syncthreads();

    // compute: batch 4 k-steps of fragments (8 independent LDS.128), then math
    #pragma unroll 4
    for (int kb = 0; kb < 16; kb++) {
        float4 af[4], wf[4];
        #pragma unroll
        for (int u = 0; u < 4; u++)
            af[u] = *(const float4*)&As[kb * 4 + u][tr * 4];
        #pragma unroll
        for (int u = 0; u < 4; u++)
            wf[u] = *(const float4*)&Ws[kb * 4 + u][th * 4];
        #pragma unroll
        for (int u = 0; u < 4; u++) {
            float av[4] = {af[u].x, af[u].y, af[u].z, af[u].w};
            float wv[4] = {wf[u].x, wf[u].y, wf[u].z, wf[u].w};
            #pragma unroll
            for (int c = 0; c < 4; c++)
                #pragma unroll
                for (int r = 0; r < 4; r++)
                    acc[c][r] = fmaf(wv[c], av[r], acc[c][r]);
        }
    }

    float* outg = (isY ? nhyT_g : hxT_g) + kc * (HH * BN);
    #pragma unroll
    for (int c = 0; c < 4; c++) {
        const int h = h0 + th * 4 + c;
        float4 o;
        if (isY) {
            o.x = -acc[c][0]; o.y = -acc[c][1];
            o.z = -acc[c][2]; o.w = -acc[c][3];
        } else {
            float bb = (kc == 0) ? b1[h] : 0.f;
            o.x = acc[c][0] + bb; o.y = acc[c][1] + bb;
            o.z = acc[c][2] + bb; o.w = acc[c][3] + bb;
        }
        *(float4*)(outg + h * BN + r0 + tr * 4) = o;
    }
}

// ---------------------------------------------------------------------------
// main: partial[z][i,j] = sum_{h in chunk z} max(hx[i,h], -hy[j,h])*w2[h]
//                         + sum_{h in chunk z} hy[j,h]*w2[h]        (gy part)
// grid (4 j-tiles, 8 i-tiles, 8 h-chunks) = 256 blocks, 256 threads.
// block tile 64i x 128j x 64h; thread tile 4i x 8j (j split {lo, hi+64}).
// staging adds the two K-halves produced by prep. Fragment double-buffered.
// ---------------------------------------------------------------------------
__global__ void __launch_bounds__(256, 2) main_kernel(const float* __restrict__ W2)
{
    __shared__ float Axs[32][64];    // [h][i]
    __shared__ float Bys[32][128];   // [h][j] (negated hy)
    __shared__ float w2s[32];
    __shared__ float gybuf[2][128];

    const int j0 = blockIdx.x * 128;
    const int i0 = blockIdx.y * 64;
    const int hb = blockIdx.z * 64;

    const int tid = threadIdx.x;
    const int ti  = tid >> 4;    // 0..15 : i frag = ti*4
    const int tj  = tid & 15;    // j frags = tj*4 and 64 + tj*4
    const int gq  = tid >> 7;    // 0..1 gy strip
    const int gj  = tid & 127;   // gy j index

    float acc[4][8] = {};
    float gyp = 0.f;

    for (int s = 0; s < 2; s++) {
        const int h0 = hb + s * 32;
        __syncthreads();
        // stage hx chunk [32h x 64i] = half0 + half1
        #pragma unroll
        for (int m = 0; m < 2; m++) {
            int t = tid + 256 * m;          // 0..511
            int h = t >> 4, q = t & 15;
            const float* base = hxT_g + (h0 + h) * BN + i0 + q * 4;
            float4 u = *(const float4*)base;
            float4 v = *(const float4*)(base + HH * BN);
            u.x += v.x; u.y += v.y; u.z += v.z; u.w += v.w;
            *(float4*)&Axs[h][q * 4] = u;
        }
        // stage -hy chunk [32h x 128j] = half0 + half1
        #pragma unroll
        for (int m = 0; m < 4; m++) {
            int t = tid + 256 * m;          // 0..1023
            int h = t >> 5, q = t & 31;
            const float* base = nhyT_g + (h0 + h) * BN + j0 + q * 4;
            float4 u = *(const float4*)base;
            float4 v = *(const float4*)(base + HH * BN);
            u.x += v.x; u.y += v.y; u.z += v.z; u.w += v.w;
            *(float4*)&Bys[h][q * 4] = u;
        }
        if (tid < 32) w2s[tid] = W2[h0 + tid];
        __syncthreads();

        // fragment double-buffer over h (registers fit at 256 threads)
        float4 aF[2], b0F[2], b1F[2];
        aF[0]  = *(const float4*)&Axs[0][ti * 4];
        b0F[0] = *(const float4*)&Bys[0][tj * 4];
        b1F[0] = *(const float4*)&Bys[0][64 + tj * 4];
        #pragma unroll 8
        for (int h = 0; h < 32; h++) {
            const int cur = h & 1, nxt = cur ^ 1;
            if (h < 31) {
                aF[nxt]  = *(const float4*)&Axs[h + 1][ti * 4];
                b0F[nxt] = *(const float4*)&Bys[h + 1][tj * 4];
                b1F[nxt] = *(const float4*)&Bys[h + 1][64 + tj * 4];
            }
            const float w = w2s[h];
            float av[4] = {aF[cur].x, aF[cur].y, aF[cur].z, aF[cur].w};
            float bv[8] = {b0F[cur].x, b0F[cur].y, b0F[cur].z, b0F[cur].w,
                           b1F[cur].x, b1F[cur].y, b1F[cur].z, b1F[cur].w};
            #pragma unroll
            for (int r = 0; r < 4; r++)
                #pragma unroll
                for (int c = 0; c < 8; c++)
                    acc[r][c] = fmaf(fmaxf(av[r], bv[c]), w, acc[r][c]);
        }

        // gy partial: strip gq covers h = gq*16 .. gq*16+15 of this stage
        #pragma unroll
        for (int hh = 0; hh < 16; hh++) {
            int h = gq * 16 + hh;
            gyp = fmaf(Bys[h][gj], w2s[h], gyp);   // accumulates -(hy*w2)
        }
    }

    __syncthreads();
    gybuf[gq][gj] = gyp;
    __syncthreads();

    float gyv[8];
    #pragma unroll
    for (int c = 0; c < 8; c++) {
        int jl = (c < 4) ? (tj * 4 + c) : (64 + tj * 4 + (c - 4));
        gyv[c] = -(gybuf[0][jl] + gybuf[1][jl]);
    }

    float* p = part_g + blockIdx.z * (BN * BN);
    #pragma unroll
    for (int r = 0; r < 4; r++) {
        float4 o0, o1;
        o0.x = acc[r][0] + gyv[0];
        o0.y = acc[r][1] + gyv[1];
        o0.z = acc[r][2] + gyv[2];
        o0.w = acc[r][3] + gyv[3];
        o1.x = acc[r][4] + gyv[4];
        o1.y = acc[r][5] + gyv[5];
        o1.z = acc[r][6] + gyv[6];
        o1.w = acc[r][7] + gyv[7];
        const int row = i0 + ti * 4 + r;
        *(float4*)(p + row * BN + j0 + tj * 4) = o0;
        *(float4*)(p + row * BN + j0 + 64 + tj * 4) = o1;
    }
}

// ---------------------------------------------------------------------------
// reduce: out = sum of 8 partials + b2
// ---------------------------------------------------------------------------
__global__ void __launch_bounds__(256) reduce_kernel(
    const float* __restrict__ b2, float* __restrict__ out)
{
    int idx = blockIdx.x * 256 + threadIdx.x;     // float4 index, 65536 total
    const float4* p = (const float4*)part_g;
    float4 s = p[idx];
    #pragma unroll
    for (int k = 1; k < 8; k++) {
        float4 v = p[idx + k * 65536];
        s.x += v.x; s.y += v.y; s.z += v.z; s.w += v.w;
    }
    float bb = b2[0];
    s.x += bb; s.y += bb; s.z += bb; s.w += bb;
    ((float4*)out)[idx] = s;
}

// ---------------------------------------------------------------------------
extern "C" void kernel_launch(void* const* d_in, const int* in_sizes, int n_in,
                              void* d_out, int out_size)
{
    const float* x  = (const float*)d_in[0];
    const float* y  = (const float*)d_in[1];
    const float* W1 = (const float*)d_in[2];
    const float* b1 = (const float*)d_in[3];
    const float* W2 = (const float*)d_in[4];
    const float* b2 = (const float*)d_in[5];
    float* out = (float*)d_out;

    prep_kernel<<<dim3(16, 8, 2), 256>>>(x, y, W1, b1);
    main_kernel<<<dim3(4, 8, 8), 256>>>(W2);
    reduce_kernel<<<256, 256>>>(b2, out);
}